// round 7
// baseline (speedup 1.0000x reference)
#include <cuda_runtime.h>

#define T_  128
#define B_  2048
#define F_  128
#define H_  64
#define A_  15
#define TB_ (T_*B_)
#define G_  256   // 4*H gates

// Scratch (allocation-free rule: __device__ globals)
__device__ float g_gin[(size_t)TB_ * G_];   // precomputed input-gate preactivations
__device__ float g_z[(size_t)TB_ * H_];     // LSTM hidden outputs per step

// ---------------------------------------------------------------------------
// math helpers
// ---------------------------------------------------------------------------
__device__ __forceinline__ float fsig(float x) {
    return __fdividef(1.0f, 1.0f + __expf(-x));
}
__device__ __forceinline__ float ftanh_fast(float x) {
    float y;
    asm("tanh.approx.f32 %0, %1;" : "=f"(y) : "f"(x));
    return y;
}
__device__ __forceinline__ unsigned tf32_rna(float x) {
    unsigned u; asm("cvt.rna.tf32.f32 %0, %1;" : "=r"(u) : "f"(x)); return u;
}
__device__ __forceinline__ float tf32f(float x) {
    return __uint_as_float(tf32_rna(x));
}
// d += a (m16k8, tf32) * b (k8n8, tf32)
__device__ __forceinline__ void mma8(float* d, const unsigned* a, unsigned b0, unsigned b1) {
    asm("mma.sync.aligned.m16n8k8.row.col.f32.tf32.tf32.f32 "
        "{%0,%1,%2,%3}, {%4,%5,%6,%7}, {%8,%9}, {%0,%1,%2,%3};"
        : "+f"(d[0]), "+f"(d[1]), "+f"(d[2]), "+f"(d[3])
        : "r"(a[0]), "r"(a[1]), "r"(a[2]), "r"(a[3]), "r"(b0), "r"(b1));
}
__device__ __forceinline__ void cp16(float* dst_smem, const float* src) {
    unsigned s = (unsigned)__cvta_generic_to_shared(dst_smem);
    asm volatile("cp.async.cg.shared.global [%0], [%1], 16;" :: "r"(s), "l"(src));
}
__device__ __forceinline__ void split2(float v, unsigned& hi, unsigned& lo) {
    hi = tf32_rna(v);
    lo = tf32_rna(v - __uint_as_float(hi));
}

// ---------------------------------------------------------------------------
// Kernel 1: fused MLP encoder + input-gate GEMM, tf32 mma.
// B operands FRAGMENT-PACKED in smem: frag[kt][ntp][lane] float4 =
// {b0(nt=2ntp), b1(2ntp), b0(2ntp+1), b1(2ntp+1)} -> 1 LDS.128 per 2 n-tiles.
// S1/S2: 2-term A split. S3: 1-term (ys pre-rounded, Wih rounded at repack).
// 256 threads (8 warps), 128 rows/block, 2048 blocks, 2 blocks/SM.
// smem (floats), 27520 = 110080 B:
//   XS   0     : per-warp xs 2-buf [8w][2][16][36] = 9216 ; later ys [128][68]
//   FR   9216  : W1 frags 8192 -> W2 frags 4096 -> (with H1) Wih frags 16384
//   H1   18432 : h1 [128][68] = 8704
//   BIAS 27136 : 384 (gin-bias 256 | b1 64 | b2 64)
// ---------------------------------------------------------------------------
#define ENC_XS   0
#define ENC_FR   9216
#define ENC_H1   18432
#define ENC_BIAS 27136
#define ENC_SMEM_F 27520

__global__ __launch_bounds__(256, 2)
void k_encode(const float* __restrict__ x,
              const float* __restrict__ W1, const float* __restrict__ b1,
              const float* __restrict__ W2, const float* __restrict__ b2,
              const float* __restrict__ Wih, const float* __restrict__ bih,
              const float* __restrict__ bhh) {
    extern __shared__ float sm[];
    float* fr   = sm + ENC_FR;
    float* h1   = sm + ENC_H1;
    float* ys   = sm + ENC_XS;     // reuses xs region after S1
    float* bias = sm + ENC_BIAS;

    const int tid  = threadIdx.x;
    const int lane = tid & 31;
    const int w    = tid >> 5;
    const int row0 = blockIdx.x * 128;
    const int qr   = lane >> 2;    // 0..7
    const int qc   = lane & 3;     // 0..3
    const int m0   = w * 16;       // warp's private row tile

    // per-warp xs double buffer: [2][16][36]
    float* xw = sm + ENC_XS + w * 1152;
    const float* xg = x + (size_t)(row0 + m0) * F_;

    // issue quarter loads q0,q1 (per-warp cp.async groups)
    #pragma unroll
    for (int q = 0; q < 2; q++) {
        float* dst = xw + q * 576;
        #pragma unroll
        for (int j = 0; j < 4; j++) {
            int idx = lane + j*32;           // float4 index 0..127
            int r = idx >> 3, c4 = (idx & 7) * 4;
            cp16(dst + r*36 + c4, xg + r*F_ + q*32 + c4);
        }
        asm volatile("cp.async.commit_group;");
    }

    // W1 -> fragment-packed (tf32-rounded) + biases
    for (int i = tid; i < F_*H_; i += 256) {
        int k = i >> 6, n = i & 63;
        int kt = k >> 3, rr = k & 7, s = rr >> 2, c2 = rr & 3;
        int nt = n >> 3, r2 = n & 7;
        fr[((kt*4 + (nt>>1))*32 + r2*4 + c2)*4 + (nt&1)*2 + s] = tf32f(W1[i]);
    }
    for (int i = tid; i < G_; i += 256) bias[i] = bih[i] + bhh[i];
    for (int i = tid; i < H_;  i += 256) { bias[256+i] = b1[i]; bias[320+i] = b2[i]; }
    __syncthreads();

    // ================= S1: h1 = tanh(x @ W1 + b1), K=128, 2-term =========
    {
        float acc[8][4];
        #pragma unroll
        for (int nt = 0; nt < 8; nt++)
            #pragma unroll
            for (int j = 0; j < 4; j++) acc[nt][j] = 0.f;

        #pragma unroll
        for (int q = 0; q < 4; q++) {
            if (q < 3) asm volatile("cp.async.wait_group 1;");
            else       asm volatile("cp.async.wait_group 0;");
            __syncwarp();
            float* xb = xw + (q & 1) * 576;
            #pragma unroll
            for (int kt2 = 0; kt2 < 4; kt2++) {
                int k0 = kt2 * 8;            // local col in quarter
                int ktg = q*4 + kt2;         // global k-tile
                float a0 = xb[qr*36 + k0 + qc];
                float a1 = xb[(qr+8)*36 + k0 + qc];
                float a2 = xb[qr*36 + k0 + qc + 4];
                float a3 = xb[(qr+8)*36 + k0 + qc + 4];
                unsigned ahi[4], alo[4];
                split2(a0, ahi[0], alo[0]); split2(a1, ahi[1], alo[1]);
                split2(a2, ahi[2], alo[2]); split2(a3, ahi[3], alo[3]);
                #pragma unroll
                for (int ntp = 0; ntp < 4; ntp++) {
                    float4 bb = *(float4*)&fr[((ktg*4 + ntp)*32 + lane)*4];
                    unsigned b0 = __float_as_uint(bb.x), b1 = __float_as_uint(bb.y);
                    unsigned b2_ = __float_as_uint(bb.z), b3 = __float_as_uint(bb.w);
                    mma8(acc[2*ntp],   ahi, b0, b1);
                    mma8(acc[2*ntp],   alo, b0, b1);
                    mma8(acc[2*ntp+1], ahi, b2_, b3);
                    mma8(acc[2*ntp+1], alo, b2_, b3);
                }
            }
            __syncwarp();
            if (q < 2) {   // refill this buffer with quarter q+2
                float* dst = xw + (q & 1) * 576;
                #pragma unroll
                for (int j = 0; j < 4; j++) {
                    int idx = lane + j*32;
                    int r = idx >> 3, c4 = (idx & 7) * 4;
                    cp16(dst + r*36 + c4, xg + r*F_ + (q+2)*32 + c4);
                }
                asm volatile("cp.async.commit_group;");
            }
        }
        #pragma unroll
        for (int nt = 0; nt < 8; nt++) {
            int c = nt*8 + 2*qc;
            float bb0 = bias[256+c], bb1 = bias[256+c+1];
            *(float2*)&h1[(m0+qr)*68 + c] =
                make_float2(ftanh_fast(acc[nt][0]+bb0), ftanh_fast(acc[nt][1]+bb1));
            *(float2*)&h1[(m0+qr+8)*68 + c] =
                make_float2(ftanh_fast(acc[nt][2]+bb0), ftanh_fast(acc[nt][3]+bb1));
        }
    }
    __syncthreads();                    // all warps done with W1 frags
    // W2 -> fragment-packed
    for (int i = tid; i < H_*H_; i += 256) {
        int k = i >> 6, n = i & 63;
        int kt = k >> 3, rr = k & 7, s = rr >> 2, c2 = rr & 3;
        int nt = n >> 3, r2 = n & 7;
        fr[((kt*4 + (nt>>1))*32 + r2*4 + c2)*4 + (nt&1)*2 + s] = tf32f(W2[i]);
    }
    __syncthreads();

    // ========= S2: ys = tf32(tanh(h1 @ W2 + b2)), K=64, 2-term ===========
    {
        float acc[8][4];
        #pragma unroll
        for (int nt = 0; nt < 8; nt++)
            #pragma unroll
            for (int j = 0; j < 4; j++) acc[nt][j] = 0.f;

        #pragma unroll 2
        for (int kt = 0; kt < 8; kt++) {
            int k0 = kt * 8;
            float a0 = h1[(m0+qr)*68 + k0 + qc];
            float a1 = h1[(m0+qr+8)*68 + k0 + qc];
            float a2 = h1[(m0+qr)*68 + k0 + qc + 4];
            float a3 = h1[(m0+qr+8)*68 + k0 + qc + 4];
            unsigned ahi[4], alo[4];
            split2(a0, ahi[0], alo[0]); split2(a1, ahi[1], alo[1]);
            split2(a2, ahi[2], alo[2]); split2(a3, ahi[3], alo[3]);
            #pragma unroll
            for (int ntp = 0; ntp < 4; ntp++) {
                float4 bb = *(float4*)&fr[((kt*4 + ntp)*32 + lane)*4];
                unsigned b0 = __float_as_uint(bb.x), b1 = __float_as_uint(bb.y);
                unsigned b2_ = __float_as_uint(bb.z), b3 = __float_as_uint(bb.w);
                mma8(acc[2*ntp],   ahi, b0, b1);
                mma8(acc[2*ntp],   alo, b0, b1);
                mma8(acc[2*ntp+1], ahi, b2_, b3);
                mma8(acc[2*ntp+1], alo, b2_, b3);
            }
        }
        // store ys PRE-ROUNDED to tf32 (S3 is 1-term; loads need no cvt)
        #pragma unroll
        for (int nt = 0; nt < 8; nt++) {
            int c = nt*8 + 2*qc;
            float bb0 = bias[320+c], bb1 = bias[320+c+1];
            *(float2*)&ys[(m0+qr)*68 + c] =
                make_float2(tf32f(ftanh_fast(acc[nt][0]+bb0)),
                            tf32f(ftanh_fast(acc[nt][1]+bb1)));
            *(float2*)&ys[(m0+qr+8)*68 + c] =
                make_float2(tf32f(ftanh_fast(acc[nt][2]+bb0)),
                            tf32f(ftanh_fast(acc[nt][3]+bb1)));
        }
    }
    __syncthreads();                    // W2 frags + h1 now dead everywhere

    // Wih -> fragment-packed directly from gmem (L2-resident), tf32-rounded.
    // Task (n, kt): read 8 floats Wih[n][kt*8..+7], scatter as 4 STS.64.
    #pragma unroll
    for (int j = 0; j < 8; j++) {
        int tsk = tid + j*256;          // 0..2047
        int n = tsk & 255, kt = tsk >> 8;
        int r2 = n & 7, ntg = n >> 3;
        const float4* src = (const float4*)(Wih + n*H_ + kt*8);
        float4 a = src[0], b = src[1];
        int D = ((kt*16 + (ntg>>1))*32 + r2*4)*4 + (ntg&1)*2;
        *(float2*)&fr[D+0]  = make_float2(tf32f(a.x), tf32f(b.x));
        *(float2*)&fr[D+4]  = make_float2(tf32f(a.y), tf32f(b.y));
        *(float2*)&fr[D+8]  = make_float2(tf32f(a.z), tf32f(b.z));
        *(float2*)&fr[D+12] = make_float2(tf32f(a.w), tf32f(b.w));
    }
    __syncthreads();

    // ===== S3: gin = ys @ Wih^T + bias, K=64, N=256, 1-term, zero cvt ====
    #pragma unroll 1
    for (int ch = 0; ch < 4; ch++) {
        float acc[8][4];
        #pragma unroll
        for (int nt = 0; nt < 8; nt++)
            #pragma unroll
            for (int j = 0; j < 4; j++) acc[nt][j] = 0.f;

        #pragma unroll 2
        for (int kt = 0; kt < 8; kt++) {
            int k0 = kt * 8;
            unsigned a[4];
            a[0] = __float_as_uint(ys[(m0+qr)*68 + k0 + qc]);
            a[1] = __float_as_uint(ys[(m0+qr+8)*68 + k0 + qc]);
            a[2] = __float_as_uint(ys[(m0+qr)*68 + k0 + qc + 4]);
            a[3] = __float_as_uint(ys[(m0+qr+8)*68 + k0 + qc + 4]);
            #pragma unroll
            for (int ntp = 0; ntp < 4; ntp++) {
                int ntpg = ch*4 + ntp;
                float4 bb = *(float4*)&fr[((kt*16 + ntpg)*32 + lane)*4];
                mma8(acc[2*ntp],   a, __float_as_uint(bb.x), __float_as_uint(bb.y));
                mma8(acc[2*ntp+1], a, __float_as_uint(bb.z), __float_as_uint(bb.w));
            }
        }
        #pragma unroll
        for (int nt = 0; nt < 8; nt++) {
            int r = row0 + m0 + qr;
            int c = ch*64 + nt*8 + 2*qc;
            float bb0 = bias[c], bb1 = bias[c+1];
            *(float2*)&g_gin[(size_t)r*G_ + c] =
                make_float2(acc[nt][0] + bb0, acc[nt][1] + bb1);
            *(float2*)&g_gin[(size_t)(r+8)*G_ + c] =
                make_float2(acc[nt][2] + bb0, acc[nt][3] + bb1);
        }
    }
}

// ---------------------------------------------------------------------------
// Kernel 2: LSTM recurrence, tf32 mma (1-term h). 256 threads (8 warps),
// 16 batch rows/block, 128 blocks. hsh stored PRE-ROUNDED tf32 and
// PRE-MASKED -> gates MMA does raw loads, no cvt, no mask phase.
// ---------------------------------------------------------------------------
#define LS_HSH  0
#define LS_GS   1088
#define LS_GINB (LS_GS + 16*264)           // 5312
#define LS_DONE (LS_GINB + 2*16*G_)        // 13504
#define LS_SMEM_F (LS_DONE + T_*16)        // 15552

__global__ __launch_bounds__(256, 1)
void k_lstm(const float* __restrict__ done,
            const float* __restrict__ h0, const float* __restrict__ c0,
            const float* __restrict__ Whh, float* __restrict__ out) {
    extern __shared__ float sm[];
    float* hsh    = sm + LS_HSH;
    float* gs     = sm + LS_GS;
    float* ginb   = sm + LS_GINB;
    float* done_s = sm + LS_DONE;

    const int tid  = threadIdx.x;
    const int lane = tid & 31;
    const int w    = tid >> 5;
    const int b0   = blockIdx.x * 16;
    const int qr   = lane >> 2, qc = lane & 3;

    // Whh fragments: warp w owns gate cols [w*32, w*32+32)
    unsigned bf0[8][4], bf1[8][4];
    #pragma unroll
    for (int kt = 0; kt < 8; kt++)
        #pragma unroll
        for (int nt = 0; nt < 4; nt++) {
            int n = w*32 + nt*8 + qr, k = kt*8 + qc;
            bf0[kt][nt] = tf32_rna(Whh[n*H_ + k]);
            bf1[kt][nt] = tf32_rna(Whh[n*H_ + k + 4]);
        }

    for (int i = tid; i < T_*16; i += 256)
        done_s[i] = done[(i>>4)*B_ + b0 + (i&15)];

    // cell ownership: thread -> (row rC, units u0..u0+3)
    const int rC = tid >> 4, u0 = (tid & 15) * 4;
    const float mk0 = 1.0f - done[b0 + rC];     // step-0 mask, direct gmem
    float c_reg[4], hlast[4];
    #pragma unroll
    for (int i = 0; i < 4; i++) {
        c_reg[i] = c0[(b0 + rC)*H_ + u0 + i] * mk0;
        hsh[rC*68 + u0 + i] = tf32f(h0[(b0 + rC)*H_ + u0 + i]) * mk0;
        hlast[i] = 0.f;
    }

    // prologue: prefetch gin[t=0]
    {
        const float* src = g_gin + (size_t)b0 * G_;
        #pragma unroll
        for (int j = 0; j < 4; j++) {
            int q = tid + j*256;
            cp16(ginb + q*4, src + q*4);
        }
        asm volatile("cp.async.commit_group;");
    }
    __syncthreads();

    for (int t = 0; t < T_; t++) {
        // prefetch gin[t+1]
        if (t + 1 < T_) {
            float* dst = ginb + ((t+1)&1) * (16*G_);
            const float* src = g_gin + (size_t)((t+1)*B_ + b0) * G_;
            #pragma unroll
            for (int j = 0; j < 4; j++) {
                int q = tid + j*256;
                cp16(dst + q*4, src + q*4);
            }
            asm volatile("cp.async.commit_group;");
        }

        // gates_rec = h @ Whh^T  (m16 x n32 per warp; hsh pre-rounded+masked)
        float acc[4][4];
        #pragma unroll
        for (int nt = 0; nt < 4; nt++)
            #pragma unroll
            for (int j = 0; j < 4; j++) acc[nt][j] = 0.f;

        #pragma unroll
        for (int kt = 0; kt < 8; kt++) {
            int k0 = kt*8;
            unsigned a[4];
            a[0] = __float_as_uint(hsh[qr*68 + k0 + qc]);
            a[1] = __float_as_uint(hsh[(qr+8)*68 + k0 + qc]);
            a[2] = __float_as_uint(hsh[qr*68 + k0 + qc + 4]);
            a[3] = __float_as_uint(hsh[(qr+8)*68 + k0 + qc + 4]);
            #pragma unroll
            for (int nt = 0; nt < 4; nt++)
                mma8(acc[nt], a, bf0[kt][nt], bf1[kt][nt]);
        }
        #pragma unroll
        for (int nt = 0; nt < 4; nt++) {
            int c = w*32 + nt*8 + 2*qc;
            *(float2*)&gs[qr*264 + c]     = make_float2(acc[nt][0], acc[nt][1]);
            *(float2*)&gs[(qr+8)*264 + c] = make_float2(acc[nt][2], acc[nt][3]);
        }

        if (t + 1 < T_) asm volatile("cp.async.wait_group 1;");
        else            asm volatile("cp.async.wait_group 0;");
        __syncthreads();

        // cell update (gate order i,f,g,o); float4 gate loads
        const float* gv = ginb + (t&1)*(16*G_) + rC*G_;
        float mn = 1.0f;
        if (t + 1 < T_) mn = 1.0f - done_s[(t+1)*16 + rC];

        float4 gi4 = *(const float4*)&gs[rC*264 + u0];
        float4 gf4 = *(const float4*)&gs[rC*264 + 64 + u0];
        float4 gg4 = *(const float4*)&gs[rC*264 + 128 + u0];
        float4 go4 = *(const float4*)&gs[rC*264 + 192 + u0];
        float4 vi4 = *(const float4*)&gv[u0];
        float4 vf4 = *(const float4*)&gv[64 + u0];
        float4 vg4 = *(const float4*)&gv[128 + u0];
        float4 vo4 = *(const float4*)&gv[192 + u0];

        float gi[4] = {gi4.x+vi4.x, gi4.y+vi4.y, gi4.z+vi4.z, gi4.w+vi4.w};
        float gf[4] = {gf4.x+vf4.x, gf4.y+vf4.y, gf4.z+vf4.z, gf4.w+vf4.w};
        float gg[4] = {gg4.x+vg4.x, gg4.y+vg4.y, gg4.z+vg4.z, gg4.w+vg4.w};
        float go[4] = {go4.x+vo4.x, go4.y+vo4.y, go4.z+vo4.z, go4.w+vo4.w};

        float hn[4], hr[4];
        #pragma unroll
        for (int i = 0; i < 4; i++) {
            float cn = fsig(gf[i])*c_reg[i] + fsig(gi[i])*ftanh_fast(gg[i]);
            hn[i] = fsig(go[i])*ftanh_fast(cn);
            c_reg[i] = cn * mn;                 // pre-mask for next step
            hr[i] = tf32f(hn[i]) * mn;          // pre-round + pre-mask
            hlast[i] = hn[i];
        }
        *(float4*)&g_z[(size_t)(t*B_ + b0 + rC)*H_ + u0] =
            make_float4(hn[0], hn[1], hn[2], hn[3]);
        *(float4*)&hsh[rC*68 + u0] = make_float4(hr[0], hr[1], hr[2], hr[3]);
        __syncthreads();
    }

    // epilogue: hT, cT (layout: logits | vf | hT | cT), full precision
    const size_t OH = (size_t)TB_ * 16;
    #pragma unroll
    for (int i = 0; i < 4; i++) {
        out[OH + (size_t)(b0 + rC)*H_ + u0 + i]                 = hlast[i];
        out[OH + (size_t)B_*H_ + (size_t)(b0 + rC)*H_ + u0 + i] = c_reg[i];
    }
}

// ---------------------------------------------------------------------------
// Kernel 3: actor/critic heads.
// ---------------------------------------------------------------------------
__global__ __launch_bounds__(128)
void k_heads(const float* __restrict__ Wa, const float* __restrict__ ba,
             const float* __restrict__ Wc, const float* __restrict__ bc,
             float* __restrict__ out) {
    __shared__ float ws[H_*16];
    __shared__ float zs[128*65];
    const int tid  = threadIdx.x;
    const int row0 = blockIdx.x * 128;

    for (int i = tid; i < 128*H_; i += 128) zs[(i>>6)*65 + (i&63)] = g_z[(size_t)row0*H_ + i];
    for (int i = tid; i < H_*16; i += 128) {
        int k = i >> 4, j = i & 15;
        ws[i] = (j < 15) ? Wa[k*A_ + j] : Wc[k];
    }
    __syncthreads();

    float acc[16];
    #pragma unroll
    for (int j = 0; j < 15; j++) acc[j] = ba[j];
    acc[15] = bc[0];
    #pragma unroll 4
    for (int k = 0; k < H_; k++) {
        float a = zs[tid*65 + k];
        #pragma unroll
        for (int j = 0; j < 16; j++) acc[j] = fmaf(a, ws[k*16 + j], acc[j]);
    }
    const size_t r = (size_t)row0 + tid;
    #pragma unroll
    for (int j = 0; j < 15; j++) out[r*A_ + j] = acc[j];
    out[(size_t)TB_*A_ + r] = acc[15];
}

// ---------------------------------------------------------------------------
extern "C" void kernel_launch(void* const* d_in, const int* in_sizes, int n_in,
                              void* d_out, int out_size) {
    const float* x    = (const float*)d_in[0];
    const float* done = (const float*)d_in[1];
    const float* h0   = (const float*)d_in[2];
    const float* c0   = (const float*)d_in[3];
    const float* W1   = (const float*)d_in[4];
    const float* b1   = (const float*)d_in[5];
    const float* W2   = (const float*)d_in[6];
    const float* b2   = (const float*)d_in[7];
    const float* Wih  = (const float*)d_in[8];
    const float* bih  = (const float*)d_in[9];
    const float* Whh  = (const float*)d_in[10];
    const float* bhh  = (const float*)d_in[11];
    const float* Wa   = (const float*)d_in[12];
    const float* ba   = (const float*)d_in[13];
    const float* Wc   = (const float*)d_in[14];
    const float* bc   = (const float*)d_in[15];
    float* out = (float*)d_out;

    cudaFuncSetAttribute(k_encode, cudaFuncAttributeMaxDynamicSharedMemorySize, ENC_SMEM_F*4);
    cudaFuncSetAttribute(k_lstm,   cudaFuncAttributeMaxDynamicSharedMemorySize, LS_SMEM_F*4);

    k_encode<<<TB_/128, 256, ENC_SMEM_F*4>>>(x, W1, b1, W2, b2, Wih, bih, bhh);
    k_lstm<<<B_/16, 256, LS_SMEM_F*4>>>(done, h0, c0, Whh, out);
    k_heads<<<TB_/128, 128>>>(Wa, ba, Wc, bc, out);
}

// round 8
// speedup vs baseline: 1.1152x; 1.1152x over previous
#include <cuda_runtime.h>

#define T_  128
#define B_  2048
#define F_  128
#define H_  64
#define A_  15
#define TB_ (T_*B_)
#define G_  256   // 4*H gates

// Scratch (allocation-free rule: __device__ globals)
__device__ float g_gin[(size_t)TB_ * G_];   // precomputed input-gate preactivations
__device__ float g_z[(size_t)TB_ * H_];     // LSTM hidden outputs per step

// ---------------------------------------------------------------------------
// math helpers
// ---------------------------------------------------------------------------
__device__ __forceinline__ float ftanh_fast(float x) {
    float y;
    asm("tanh.approx.f32 %0, %1;" : "=f"(y) : "f"(x));
    return y;
}
// sigmoid(x) = 0.5*tanh(x/2) + 0.5 : 1 MUFU + FMAs (vs EX2+RCP)
__device__ __forceinline__ float fsig_fast(float x) {
    return fmaf(0.5f, ftanh_fast(0.5f * x), 0.5f);
}
__device__ __forceinline__ unsigned tf32_rna(float x) {
    unsigned u; asm("cvt.rna.tf32.f32 %0, %1;" : "=r"(u) : "f"(x)); return u;
}
__device__ __forceinline__ float tf32f(float x) {
    return __uint_as_float(tf32_rna(x));
}
// d += a (m16k8, tf32) * b (k8n8, tf32)
__device__ __forceinline__ void mma8(float* d, const unsigned* a, unsigned b0, unsigned b1) {
    asm("mma.sync.aligned.m16n8k8.row.col.f32.tf32.tf32.f32 "
        "{%0,%1,%2,%3}, {%4,%5,%6,%7}, {%8,%9}, {%0,%1,%2,%3};"
        : "+f"(d[0]), "+f"(d[1]), "+f"(d[2]), "+f"(d[3])
        : "r"(a[0]), "r"(a[1]), "r"(a[2]), "r"(a[3]), "r"(b0), "r"(b1));
}
__device__ __forceinline__ void cp16(float* dst_smem, const float* src) {
    unsigned s = (unsigned)__cvta_generic_to_shared(dst_smem);
    asm volatile("cp.async.cg.shared.global [%0], [%1], 16;" :: "r"(s), "l"(src));
}
__device__ __forceinline__ void split2(float v, unsigned& hi, unsigned& lo) {
    hi = tf32_rna(v);
    lo = tf32_rna(v - __uint_as_float(hi));
}

// ---------------------------------------------------------------------------
// Kernel 1: fused MLP encoder + input-gate GEMM, tf32 mma.  (R6 version —
// scalar distinct-word B-LDS is 1-phase-optimal; fragment-packing regressed.)
// S1/S2: 2-term A split. S3: 1-term (ys and Wih pre-rounded in smem, zero cvt).
// 256 threads (8 warps), 128 rows/block, 2048 blocks, 2 blocks/SM.
// ---------------------------------------------------------------------------
#define ENC_XS   0
#define ENC_WA   9216
#define ENC_H1   18432
#define ENC_BIAS 27136
#define ENC_SMEM_F 27520

__global__ __launch_bounds__(256, 2)
void k_encode(const float* __restrict__ x,
              const float* __restrict__ W1, const float* __restrict__ b1,
              const float* __restrict__ W2, const float* __restrict__ b2,
              const float* __restrict__ Wih, const float* __restrict__ bih,
              const float* __restrict__ bhh) {
    extern __shared__ float sm[];
    float* wA   = sm + ENC_WA;
    float* h1   = sm + ENC_H1;
    float* ys   = sm + ENC_XS;     // reuses xs region after S1
    float* wg   = sm + ENC_WA;     // raw->rounded Wih after S2 (spans WA+H1)
    float* bias = sm + ENC_BIAS;

    const int tid  = threadIdx.x;
    const int lane = tid & 31;
    const int w    = tid >> 5;
    const int row0 = blockIdx.x * 128;
    const int qr   = lane >> 2;    // 0..7
    const int qc   = lane & 3;     // 0..3
    const int m0   = w * 16;       // warp's private row tile

    // per-warp xs double buffer: [2][16][36]
    float* xw = sm + ENC_XS + w * 1152;
    const float* xg = x + (size_t)(row0 + m0) * F_;

    // issue quarter loads q0,q1 (per-warp cp.async groups)
    #pragma unroll
    for (int q = 0; q < 2; q++) {
        float* dst = xw + q * 576;
        #pragma unroll
        for (int j = 0; j < 4; j++) {
            int idx = lane + j*32;           // float4 index 0..127
            int r = idx >> 3, c4 = (idx & 7) * 4;
            cp16(dst + r*36 + c4, xg + r*F_ + q*32 + c4);
        }
        asm volatile("cp.async.commit_group;");
    }

    // W1 (tf32-rounded) + biases
    for (int i = tid; i < F_*H_; i += 256) {
        int k = i >> 6, n = i & 63;
        wA[k*72 + n] = tf32f(W1[i]);
    }
    for (int i = tid; i < G_; i += 256) bias[i] = bih[i] + bhh[i];
    for (int i = tid; i < H_;  i += 256) { bias[256+i] = b1[i]; bias[320+i] = b2[i]; }
    __syncthreads();

    // ================= S1: h1 = tanh(x @ W1 + b1), K=128, 2-term =========
    {
        float acc[8][4];
        #pragma unroll
        for (int nt = 0; nt < 8; nt++)
            #pragma unroll
            for (int j = 0; j < 4; j++) acc[nt][j] = 0.f;

        #pragma unroll
        for (int q = 0; q < 4; q++) {
            if (q < 3) asm volatile("cp.async.wait_group 1;");
            else       asm volatile("cp.async.wait_group 0;");
            __syncwarp();
            float* xb = xw + (q & 1) * 576;
            #pragma unroll
            for (int kt2 = 0; kt2 < 4; kt2++) {
                int k0 = kt2 * 8;            // local col in quarter
                int bk = q*32 + k0 + qc;     // global k for B
                float a0 = xb[qr*36 + k0 + qc];
                float a1 = xb[(qr+8)*36 + k0 + qc];
                float a2 = xb[qr*36 + k0 + qc + 4];
                float a3 = xb[(qr+8)*36 + k0 + qc + 4];
                unsigned ahi[4], alo[4];
                split2(a0, ahi[0], alo[0]); split2(a1, ahi[1], alo[1]);
                split2(a2, ahi[2], alo[2]); split2(a3, ahi[3], alo[3]);
                #pragma unroll
                for (int nt = 0; nt < 8; nt++) {
                    int bn = nt*8 + qr;
                    unsigned bh0 = __float_as_uint(wA[bk*72 + bn]);
                    unsigned bh1 = __float_as_uint(wA[(bk+4)*72 + bn]);
                    mma8(acc[nt], ahi, bh0, bh1);
                    mma8(acc[nt], alo, bh0, bh1);
                }
            }
            __syncwarp();
            if (q < 2) {   // refill this buffer with quarter q+2
                float* dst = xw + (q & 1) * 576;
                #pragma unroll
                for (int j = 0; j < 4; j++) {
                    int idx = lane + j*32;
                    int r = idx >> 3, c4 = (idx & 7) * 4;
                    cp16(dst + r*36 + c4, xg + r*F_ + (q+2)*32 + c4);
                }
                asm volatile("cp.async.commit_group;");
            }
        }
        #pragma unroll
        for (int nt = 0; nt < 8; nt++) {
            int c = nt*8 + 2*qc;
            float bb0 = bias[256+c], bb1 = bias[256+c+1];
            *(float2*)&h1[(m0+qr)*68 + c] =
                make_float2(ftanh_fast(acc[nt][0]+bb0), ftanh_fast(acc[nt][1]+bb1));
            *(float2*)&h1[(m0+qr+8)*68 + c] =
                make_float2(ftanh_fast(acc[nt][2]+bb0), ftanh_fast(acc[nt][3]+bb1));
        }
    }
    __syncthreads();                    // all warps done with W1 region
    for (int i = tid; i < H_*H_; i += 256) {
        int k = i >> 6, n = i & 63;
        wA[k*72 + n] = tf32f(W2[i]);
    }
    __syncthreads();

    // ========= S2: ys = tf32(tanh(h1 @ W2 + b2)), K=64, 2-term ===========
    {
        float acc[8][4];
        #pragma unroll
        for (int nt = 0; nt < 8; nt++)
            #pragma unroll
            for (int j = 0; j < 4; j++) acc[nt][j] = 0.f;

        #pragma unroll 2
        for (int kt = 0; kt < 8; kt++) {
            int k0 = kt * 8;
            float a0 = h1[(m0+qr)*68 + k0 + qc];
            float a1 = h1[(m0+qr+8)*68 + k0 + qc];
            float a2 = h1[(m0+qr)*68 + k0 + qc + 4];
            float a3 = h1[(m0+qr+8)*68 + k0 + qc + 4];
            unsigned ahi[4], alo[4];
            split2(a0, ahi[0], alo[0]); split2(a1, ahi[1], alo[1]);
            split2(a2, ahi[2], alo[2]); split2(a3, ahi[3], alo[3]);
            #pragma unroll
            for (int nt = 0; nt < 8; nt++) {
                int bk = k0 + qc, bn = nt*8 + qr;
                unsigned bh0 = __float_as_uint(wA[bk*72 + bn]);
                unsigned bh1 = __float_as_uint(wA[(bk+4)*72 + bn]);
                mma8(acc[nt], ahi, bh0, bh1);
                mma8(acc[nt], alo, bh0, bh1);
            }
        }
        // store ys PRE-ROUNDED to tf32 (S3 is 1-term; loads need no cvt)
        #pragma unroll
        for (int nt = 0; nt < 8; nt++) {
            int c = nt*8 + 2*qc;
            float bb0 = bias[320+c], bb1 = bias[320+c+1];
            *(float2*)&ys[(m0+qr)*68 + c] =
                make_float2(tf32f(ftanh_fast(acc[nt][0]+bb0)),
                            tf32f(ftanh_fast(acc[nt][1]+bb1)));
            *(float2*)&ys[(m0+qr+8)*68 + c] =
                make_float2(tf32f(ftanh_fast(acc[nt][2]+bb0)),
                            tf32f(ftanh_fast(acc[nt][3]+bb1)));
        }
    }
    __syncthreads();                    // W2 + h1 regions now dead everywhere

    // async-load FULL raw Wih [256][68] into dead WA+H1 regions,
    // then round own elements in place (no cvt needed in S3).
    #pragma unroll
    for (int j = 0; j < 16; j++) {
        int f = tid + j*256;            // 0..4095 (float4 units)
        int n = f >> 4, c4 = (f & 15) * 4;
        cp16(wg + n*68 + c4, Wih + n*H_ + c4);
    }
    asm volatile("cp.async.commit_group;");
    asm volatile("cp.async.wait_group 0;");
    #pragma unroll
    for (int j = 0; j < 16; j++) {
        int f = tid + j*256;
        int n = f >> 4, c4 = (f & 15) * 4;
        float* p = wg + n*68 + c4;
        p[0] = tf32f(p[0]); p[1] = tf32f(p[1]);
        p[2] = tf32f(p[2]); p[3] = tf32f(p[3]);
    }
    __syncthreads();

    // ===== S3: gin = ys @ Wih^T + bias, K=64, N=256, 1-term, zero cvt ====
    #pragma unroll 1
    for (int ch = 0; ch < 4; ch++) {
        float acc[8][4];
        #pragma unroll
        for (int nt = 0; nt < 8; nt++)
            #pragma unroll
            for (int j = 0; j < 4; j++) acc[nt][j] = 0.f;

        #pragma unroll 2
        for (int kt = 0; kt < 8; kt++) {
            int k0 = kt * 8;
            unsigned a[4];
            a[0] = __float_as_uint(ys[(m0+qr)*68 + k0 + qc]);
            a[1] = __float_as_uint(ys[(m0+qr+8)*68 + k0 + qc]);
            a[2] = __float_as_uint(ys[(m0+qr)*68 + k0 + qc + 4]);
            a[3] = __float_as_uint(ys[(m0+qr+8)*68 + k0 + qc + 4]);
            #pragma unroll
            for (int nt = 0; nt < 8; nt++) {
                int bn = ch*64 + nt*8 + qr, bk = k0 + qc;
                mma8(acc[nt], a,
                     __float_as_uint(wg[bn*68 + bk]),
                     __float_as_uint(wg[bn*68 + bk + 4]));
            }
        }
        #pragma unroll
        for (int nt = 0; nt < 8; nt++) {
            int r = row0 + m0 + qr;
            int c = ch*64 + nt*8 + 2*qc;
            float bb0 = bias[c], bb1 = bias[c+1];
            *(float2*)&g_gin[(size_t)r*G_ + c] =
                make_float2(acc[nt][0] + bb0, acc[nt][1] + bb1);
            *(float2*)&g_gin[(size_t)(r+8)*G_ + c] =
                make_float2(acc[nt][2] + bb0, acc[nt][3] + bb1);
        }
    }
}

// ---------------------------------------------------------------------------
// Kernel 2: LSTM recurrence, tf32 mma (1-term h). 256 threads (8 warps),
// 16 batch rows/block, 128 blocks. hsh stored PRE-ROUNDED tf32 and
// PRE-MASKED -> gates MMA does raw loads, no cvt, no mask phase.
// Cell transcendentals ALL via tanh.approx (sigmoid = 0.5*tanh(x/2)+0.5):
// 20 MUFU-instr/warp/step instead of 32.
// ---------------------------------------------------------------------------
#define LS_HSH  0
#define LS_GS   1088
#define LS_GINB (LS_GS + 16*264)           // 5312
#define LS_DONE (LS_GINB + 2*16*G_)        // 13504
#define LS_SMEM_F (LS_DONE + T_*16)        // 15552

__global__ __launch_bounds__(256, 1)
void k_lstm(const float* __restrict__ done,
            const float* __restrict__ h0, const float* __restrict__ c0,
            const float* __restrict__ Whh, float* __restrict__ out) {
    extern __shared__ float sm[];
    float* hsh    = sm + LS_HSH;
    float* gs     = sm + LS_GS;
    float* ginb   = sm + LS_GINB;
    float* done_s = sm + LS_DONE;

    const int tid  = threadIdx.x;
    const int lane = tid & 31;
    const int w    = tid >> 5;
    const int b0   = blockIdx.x * 16;
    const int qr   = lane >> 2, qc = lane & 3;

    // Whh fragments: warp w owns gate cols [w*32, w*32+32)
    unsigned bf0[8][4], bf1[8][4];
    #pragma unroll
    for (int kt = 0; kt < 8; kt++)
        #pragma unroll
        for (int nt = 0; nt < 4; nt++) {
            int n = w*32 + nt*8 + qr, k = kt*8 + qc;
            bf0[kt][nt] = tf32_rna(Whh[n*H_ + k]);
            bf1[kt][nt] = tf32_rna(Whh[n*H_ + k + 4]);
        }

    for (int i = tid; i < T_*16; i += 256)
        done_s[i] = done[(i>>4)*B_ + b0 + (i&15)];

    // cell ownership: thread -> (row rC, units u0..u0+3)
    const int rC = tid >> 4, u0 = (tid & 15) * 4;
    const float mk0 = 1.0f - done[b0 + rC];     // step-0 mask, direct gmem
    float c_reg[4], hlast[4];
    #pragma unroll
    for (int i = 0; i < 4; i++) {
        c_reg[i] = c0[(b0 + rC)*H_ + u0 + i] * mk0;
        hsh[rC*68 + u0 + i] = tf32f(h0[(b0 + rC)*H_ + u0 + i]) * mk0;
        hlast[i] = 0.f;
    }

    // prologue: prefetch gin[t=0]
    {
        const float* src = g_gin + (size_t)b0 * G_;
        #pragma unroll
        for (int j = 0; j < 4; j++) {
            int q = tid + j*256;
            cp16(ginb + q*4, src + q*4);
        }
        asm volatile("cp.async.commit_group;");
    }
    __syncthreads();

    for (int t = 0; t < T_; t++) {
        // prefetch gin[t+1]
        if (t + 1 < T_) {
            float* dst = ginb + ((t+1)&1) * (16*G_);
            const float* src = g_gin + (size_t)((t+1)*B_ + b0) * G_;
            #pragma unroll
            for (int j = 0; j < 4; j++) {
                int q = tid + j*256;
                cp16(dst + q*4, src + q*4);
            }
            asm volatile("cp.async.commit_group;");
        }

        // gates_rec = h @ Whh^T  (m16 x n32 per warp; hsh pre-rounded+masked)
        float acc[4][4];
        #pragma unroll
        for (int nt = 0; nt < 4; nt++)
            #pragma unroll
            for (int j = 0; j < 4; j++) acc[nt][j] = 0.f;

        #pragma unroll
        for (int kt = 0; kt < 8; kt++) {
            int k0 = kt*8;
            unsigned a[4];
            a[0] = __float_as_uint(hsh[qr*68 + k0 + qc]);
            a[1] = __float_as_uint(hsh[(qr+8)*68 + k0 + qc]);
            a[2] = __float_as_uint(hsh[qr*68 + k0 + qc + 4]);
            a[3] = __float_as_uint(hsh[(qr+8)*68 + k0 + qc + 4]);
            #pragma unroll
            for (int nt = 0; nt < 4; nt++)
                mma8(acc[nt], a, bf0[kt][nt], bf1[kt][nt]);
        }
        #pragma unroll
        for (int nt = 0; nt < 4; nt++) {
            int c = w*32 + nt*8 + 2*qc;
            *(float2*)&gs[qr*264 + c]     = make_float2(acc[nt][0], acc[nt][1]);
            *(float2*)&gs[(qr+8)*264 + c] = make_float2(acc[nt][2], acc[nt][3]);
        }

        if (t + 1 < T_) asm volatile("cp.async.wait_group 1;");
        else            asm volatile("cp.async.wait_group 0;");
        __syncthreads();

        // cell update (gate order i,f,g,o); float4 gate loads
        const float* gv = ginb + (t&1)*(16*G_) + rC*G_;
        float mn = 1.0f;
        if (t + 1 < T_) mn = 1.0f - done_s[(t+1)*16 + rC];

        float4 gi4 = *(const float4*)&gs[rC*264 + u0];
        float4 gf4 = *(const float4*)&gs[rC*264 + 64 + u0];
        float4 gg4 = *(const float4*)&gs[rC*264 + 128 + u0];
        float4 go4 = *(const float4*)&gs[rC*264 + 192 + u0];
        float4 vi4 = *(const float4*)&gv[u0];
        float4 vf4 = *(const float4*)&gv[64 + u0];
        float4 vg4 = *(const float4*)&gv[128 + u0];
        float4 vo4 = *(const float4*)&gv[192 + u0];

        float gi[4] = {gi4.x+vi4.x, gi4.y+vi4.y, gi4.z+vi4.z, gi4.w+vi4.w};
        float gf[4] = {gf4.x+vf4.x, gf4.y+vf4.y, gf4.z+vf4.z, gf4.w+vf4.w};
        float gg[4] = {gg4.x+vg4.x, gg4.y+vg4.y, gg4.z+vg4.z, gg4.w+vg4.w};
        float go[4] = {go4.x+vo4.x, go4.y+vo4.y, go4.z+vo4.z, go4.w+vo4.w};

        float hn[4], hr[4];
        #pragma unroll
        for (int i = 0; i < 4; i++) {
            float cn = fsig_fast(gf[i])*c_reg[i] + fsig_fast(gi[i])*ftanh_fast(gg[i]);
            hn[i] = fsig_fast(go[i])*ftanh_fast(cn);
            c_reg[i] = cn * mn;                 // pre-mask for next step
            hr[i] = tf32f(hn[i]) * mn;          // pre-round + pre-mask
            hlast[i] = hn[i];
        }
        *(float4*)&g_z[(size_t)(t*B_ + b0 + rC)*H_ + u0] =
            make_float4(hn[0], hn[1], hn[2], hn[3]);
        *(float4*)&hsh[rC*68 + u0] = make_float4(hr[0], hr[1], hr[2], hr[3]);
        __syncthreads();
    }

    // epilogue: hT, cT (layout: logits | vf | hT | cT), full precision
    const size_t OH = (size_t)TB_ * 16;
    #pragma unroll
    for (int i = 0; i < 4; i++) {
        out[OH + (size_t)(b0 + rC)*H_ + u0 + i]                 = hlast[i];
        out[OH + (size_t)B_*H_ + (size_t)(b0 + rC)*H_ + u0 + i] = c_reg[i];
    }
}

// ---------------------------------------------------------------------------
// Kernel 3: actor/critic heads.
// ---------------------------------------------------------------------------
__global__ __launch_bounds__(128)
void k_heads(const float* __restrict__ Wa, const float* __restrict__ ba,
             const float* __restrict__ Wc, const float* __restrict__ bc,
             float* __restrict__ out) {
    __shared__ float ws[H_*16];
    __shared__ float zs[128*65];
    const int tid  = threadIdx.x;
    const int row0 = blockIdx.x * 128;

    for (int i = tid; i < 128*H_; i += 128) zs[(i>>6)*65 + (i&63)] = g_z[(size_t)row0*H_ + i];
    for (int i = tid; i < H_*16; i += 128) {
        int k = i >> 4, j = i & 15;
        ws[i] = (j < 15) ? Wa[k*A_ + j] : Wc[k];
    }
    __syncthreads();

    float acc[16];
    #pragma unroll
    for (int j = 0; j < 15; j++) acc[j] = ba[j];
    acc[15] = bc[0];
    #pragma unroll 4
    for (int k = 0; k < H_; k++) {
        float a = zs[tid*65 + k];
        #pragma unroll
        for (int j = 0; j < 16; j++) acc[j] = fmaf(a, ws[k*16 + j], acc[j]);
    }
    const size_t r = (size_t)row0 + tid;
    #pragma unroll
    for (int j = 0; j < 15; j++) out[r*A_ + j] = acc[j];
    out[(size_t)TB_*A_ + r] = acc[15];
}

// ---------------------------------------------------------------------------
extern "C" void kernel_launch(void* const* d_in, const int* in_sizes, int n_in,
                              void* d_out, int out_size) {
    const float* x    = (const float*)d_in[0];
    const float* done = (const float*)d_in[1];
    const float* h0   = (const float*)d_in[2];
    const float* c0   = (const float*)d_in[3];
    const float* W1   = (const float*)d_in[4];
    const float* b1   = (const float*)d_in[5];
    const float* W2   = (const float*)d_in[6];
    const float* b2   = (const float*)d_in[7];
    const float* Wih  = (const float*)d_in[8];
    const float* bih  = (const float*)d_in[9];
    const float* Whh  = (const float*)d_in[10];
    const float* bhh  = (const float*)d_in[11];
    const float* Wa   = (const float*)d_in[12];
    const float* ba   = (const float*)d_in[13];
    const float* Wc   = (const float*)d_in[14];
    const float* bc   = (const float*)d_in[15];
    float* out = (float*)d_out;

    cudaFuncSetAttribute(k_encode, cudaFuncAttributeMaxDynamicSharedMemorySize, ENC_SMEM_F*4);
    cudaFuncSetAttribute(k_lstm,   cudaFuncAttributeMaxDynamicSharedMemorySize, LS_SMEM_F*4);

    k_encode<<<TB_/128, 256, ENC_SMEM_F*4>>>(x, W1, b1, W2, b2, Wih, bih, bhh);
    k_lstm<<<B_/16, 256, LS_SMEM_F*4>>>(done, h0, c0, Whh, out);
    k_heads<<<TB_/128, 128>>>(Wa, ba, Wc, bc, out);
}